// round 2
// baseline (speedup 1.0000x reference)
#include <cuda_runtime.h>

typedef unsigned long long ull;

#define NEXPERTS 64
#define S_MAX    8192

// static scratch (no allocations allowed)
__device__ float g_part[2u * S_MAX * NEXPERTS];          // split-K partial logits, 4MB
__device__ int   g_idx[S_MAX];
__device__ float g_gate[S_MAX];
__device__ float g_me_partial[(S_MAX / 8) * NEXPERTS];   // per-block softmax sums
__device__ float g_laux;

__device__ __forceinline__ ull pack2(float lo, float hi) {
    ull r; asm("mov.b64 %0, {%1, %2};" : "=l"(r) : "f"(lo), "f"(hi)); return r;
}
__device__ __forceinline__ void ffma2(ull& d, ull a, ull b) {
    asm("fma.rn.f32x2 %0, %1, %2, %0;" : "+l"(d) : "l"(a), "l"(b));
}
__device__ __forceinline__ float2 unpack2(ull v) {
    float2 r; asm("mov.b64 {%0, %1}, %2;" : "=f"(r.x), "=f"(r.y) : "l"(v)); return r;
}

// ---------------------------------------------------------------------------
// Kernel 1: logits = x @ wg^T, split-K=2, FUSED with zero-fill of d_out.
// Tile: 64 tokens x 64 experts, 128 threads, micro 8 tokens x 4 experts.
// Accumulators are f32x2 packed over token pairs (FFMA2 = 2 FMAs/instr).
// The GEMM is fma-pipe-bound; the interleaved STG.128 zero stores use the
// otherwise-idle memory pipes, replacing the serial 537MB cudaMemset.
// ---------------------------------------------------------------------------
__global__ __launch_bounds__(128) void gemm_logits_zero(const float* __restrict__ x,
                                                        const float* __restrict__ wg,
                                                        int D, int S,
                                                        float4* __restrict__ zout,
                                                        size_t n4_total,
                                                        float* __restrict__ out,
                                                        size_t osz) {
    __shared__ float As[32][68];   // [k][token], padded vs bank conflicts
    __shared__ float Bs[32][68];   // [k][expert]
    const int tid = threadIdx.x;
    const int ty  = tid >> 4;      // 0..7  -> tokens ty*8 .. ty*8+7
    const int tx  = tid & 15;      // 0..15 -> experts tx*4 .. tx*4+3
    const int s0  = blockIdx.x * 64;
    const int half  = D >> 1;
    const int kbase = blockIdx.y * half;

    // zero-fill bookkeeping: this block's slice of d_out, spread over k-tiles
    const int nblk   = gridDim.x * gridDim.y;
    const int bz     = blockIdx.y * gridDim.x + blockIdx.x;
    const int n_ot   = half >> 5;                              // # of 32-wide k tiles
    const size_t per_blk4 = (n4_total + nblk - 1) / nblk;
    const size_t blk_base = (size_t)bz * per_blk4;
    const size_t blk_end  = min(blk_base + per_blk4, n4_total);
    const size_t per_ot4  = (per_blk4 + n_ot - 1) / n_ot;
    const float4 z4 = make_float4(0.f, 0.f, 0.f, 0.f);

    // tail floats (osz not multiple of 4) zeroed by one thread
    if (bz == 0 && tid == 0) {
        for (size_t i = n4_total * 4; i < osz; ++i) out[i] = 0.f;
    }

    ull acc[4][4];
#pragma unroll
    for (int i = 0; i < 4; ++i)
#pragma unroll
        for (int j = 0; j < 4; ++j) acc[i][j] = 0ull;

    int ot = 0;
    for (int kt = 0; kt < half; kt += 32, ++ot) {
#pragma unroll
        for (int r = 0; r < 4; ++r) {
            int i   = tid + r * 128;       // 0..511 float4 groups
            int row = i >> 3;              // 0..63
            int k4  = (i & 7) << 2;        // 0,4,...,28
            float4 av = *(const float4*)(x  + (size_t)(s0 + row) * D + kbase + kt + k4);
            As[k4 + 0][row] = av.x; As[k4 + 1][row] = av.y;
            As[k4 + 2][row] = av.z; As[k4 + 3][row] = av.w;
            float4 bv = *(const float4*)(wg + (size_t)row * D + kbase + kt + k4);
            Bs[k4 + 0][row] = bv.x; Bs[k4 + 1][row] = bv.y;
            Bs[k4 + 2][row] = bv.z; Bs[k4 + 3][row] = bv.w;
        }
        __syncthreads();
#pragma unroll
        for (int k = 0; k < 32; ++k) {
            ulonglong2 A0 = *(const ulonglong2*)&As[k][ty * 8];
            ulonglong2 A1 = *(const ulonglong2*)&As[k][ty * 8 + 4];
            ull a0 = A0.x, a1 = A0.y, a2 = A1.x, a3 = A1.y;
            float4 bv = *(const float4*)&Bs[k][tx * 4];
            ull b0 = pack2(bv.x, bv.x), b1 = pack2(bv.y, bv.y);
            ull b2 = pack2(bv.z, bv.z), b3 = pack2(bv.w, bv.w);
            ffma2(acc[0][0], a0, b0); ffma2(acc[0][1], a0, b1);
            ffma2(acc[0][2], a0, b2); ffma2(acc[0][3], a0, b3);
            ffma2(acc[1][0], a1, b0); ffma2(acc[1][1], a1, b1);
            ffma2(acc[1][2], a1, b2); ffma2(acc[1][3], a1, b3);
            ffma2(acc[2][0], a2, b0); ffma2(acc[2][1], a2, b1);
            ffma2(acc[2][2], a2, b2); ffma2(acc[2][3], a2, b3);
            ffma2(acc[3][0], a3, b0); ffma2(acc[3][1], a3, b1);
            ffma2(acc[3][2], a3, b2); ffma2(acc[3][3], a3, b3);
        }
        // zero-fill this k-tile's share of the output (memory pipes are idle)
        {
            size_t zo = blk_base + (size_t)ot * per_ot4 + tid;
            size_t ze = min(blk_base + (size_t)(ot + 1) * per_ot4, blk_end);
            for (; zo < ze; zo += 128) zout[zo] = z4;
        }
        __syncthreads();
    }

    float* outp = g_part + (size_t)blockIdx.y * S * NEXPERTS;
#pragma unroll
    for (int i = 0; i < 4; ++i) {
        float2 c0 = unpack2(acc[i][0]);
        float2 c1 = unpack2(acc[i][1]);
        float2 c2 = unpack2(acc[i][2]);
        float2 c3 = unpack2(acc[i][3]);
        int t0 = s0 + ty * 8 + 2 * i;
        float4 lo = make_float4(c0.x, c1.x, c2.x, c3.x);
        float4 hi = make_float4(c0.y, c1.y, c2.y, c3.y);
        *(float4*)(outp + (size_t)t0 * NEXPERTS + tx * 4)       = lo;
        *(float4*)(outp + (size_t)(t0 + 1) * NEXPERTS + tx * 4) = hi;
    }
}

// ---------------------------------------------------------------------------
// Kernel 2: per-token softmax over 64 experts, top-1 (first max = argmax),
// gate = 1/sum(exp(l - max)). One warp per token. Emits deterministic
// per-block partial sums of gates for l_aux's "me".
// ---------------------------------------------------------------------------
__global__ __launch_bounds__(256) void softmax_top1(int S) {
    __shared__ float gsh[8][64];
    const int warp = threadIdx.x >> 5;
    const int lane = threadIdx.x & 31;
    const int t = blockIdx.x * 8 + warp;

    const float* p0 = g_part + (size_t)t * NEXPERTS;
    const float* p1 = g_part + (size_t)S * NEXPERTS + (size_t)t * NEXPERTS;
    float v0 = p0[lane]      + p1[lane];
    float v1 = p0[lane + 32] + p1[lane + 32];

    float m = fmaxf(v0, v1);
#pragma unroll
    for (int o = 16; o; o >>= 1) m = fmaxf(m, __shfl_xor_sync(0xffffffffu, m, o));
    float e0 = expf(v0 - m), e1 = expf(v1 - m);
    float s = e0 + e1;
#pragma unroll
    for (int o = 16; o; o >>= 1) s += __shfl_xor_sync(0xffffffffu, s, o);

    int ix = 1 << 30;
    if (v1 == m) ix = lane + 32;
    if (v0 == m) ix = lane;          // lower index wins (jnp.argmax semantics)
#pragma unroll
    for (int o = 16; o; o >>= 1) ix = min(ix, __shfl_xor_sync(0xffffffffu, ix, o));

    float inv = 1.0f / s;
    gsh[warp][lane]      = e0 * inv;
    gsh[warp][lane + 32] = e1 * inv;
    if (lane == 0) { g_idx[t] = ix; g_gate[t] = inv; }
    __syncthreads();
    if (threadIdx.x < 64) {
        float acc = 0.f;
#pragma unroll
        for (int w = 0; w < 8; ++w) acc += gsh[w][threadIdx.x];
        g_me_partial[(size_t)blockIdx.x * 64 + threadIdx.x] = acc;
    }
}

// ---------------------------------------------------------------------------
// Kernel 3 (single block, 1024 threads): per-expert ordered rank of each token
// (cumsum of one-hot), ce counts, me reduction, l_aux — AND the sparse scatter
// of gate / dispatch values directly into the (already-zeroed) output.
// Thread (e, g): expert e = tid&63, chunk g = tid>>6 of S/16 tokens.
// Everything reduced in fixed order -> deterministic.
// ---------------------------------------------------------------------------
__global__ __launch_bounds__(1024) void scan_laux_scatter(int S, int nb, int C,
                                                          float* __restrict__ out,
                                                          long long comb_off,
                                                          long long disp_off,
                                                          int write_aux) {
    const int e = threadIdx.x & 63;
    const int g = threadIdx.x >> 6;     // 0..15
    const int chunk = S >> 4;
    const int s0 = g * chunk;

    int cnt = 0;
    for (int s = s0; s < s0 + chunk; ++s) cnt += (g_idx[s] == e);

    __shared__ int   cnt_s[16][64];
    __shared__ float me_s[16][64];
    cnt_s[g][e] = cnt;
    __syncthreads();

    int base = 0, total = 0;
#pragma unroll
    for (int gg = 0; gg < 16; ++gg) {
        int c = cnt_s[gg][e];
        if (gg < g) base += c;
        total += c;
    }
    // walk tokens; for each token routed to expert e, rank = run; scatter if kept
    int run = base;
    for (int s = s0; s < s0 + chunk; ++s) {
        if (g_idx[s] == e) {
            if (run < C) {
                size_t pos = ((size_t)s * NEXPERTS + e) * (size_t)C + run;
                out[(size_t)comb_off + pos] = g_gate[s];
                if (disp_off >= 0)
                    out[(size_t)disp_off + pos] = 1.0f;
            }
            run++;
        }
    }

    float mp = 0.f;
    for (int b = g; b < nb; b += 16) mp += g_me_partial[(size_t)b * 64 + e];
    me_s[g][e] = mp;
    __syncthreads();
    if (g == 0) {
        float me = 0.f;
#pragma unroll
        for (int gg = 0; gg < 16; ++gg) me += me_s[gg][e];
        me /= (float)S;
        float ce = (float)total / (float)S;   // counts BEFORE capacity drop
        me_s[0][e] = me * ce;
    }
    __syncthreads();
    if (threadIdx.x == 0 && write_aux) {
        float sum = 0.f;
        for (int ee = 0; ee < 64; ++ee) sum += me_s[0][ee];
        out[0] = sum * (float)NEXPERTS;       // mean(me*ce)*E^2 = sum*E
    }
}

extern "C" void kernel_launch(void* const* d_in, const int* in_sizes, int n_in,
                              void* d_out, int out_size) {
    const float* x  = (const float*)d_in[0];
    const float* wg = (const float*)d_in[1];
    const int D = in_sizes[1] / NEXPERTS;
    const int S = in_sizes[0] / D;
    const int C = (S + NEXPERTS - 1) / NEXPERTS;   // capacity_factor = 1.0
    const size_t SEC = (size_t)S * NEXPERTS * C;
    const size_t osz = (size_t)out_size;

    // output layout: [l_aux(1)][combine(SEC)][dispatch(SEC)] when sizes match
    long long comb = 0, disp = -1; int aux = 0;
    if (osz >= 2 * SEC + 1)      { aux = 1; comb = 1; disp = 1 + (long long)SEC; }
    else if (osz >= 2 * SEC)     { comb = 0; disp = (long long)SEC; }

    const size_t n4 = osz >> 2;   // float4-aligned zero-fill amount

    dim3 ggrid(S / 64, 2);
    gemm_logits_zero<<<ggrid, 128>>>(x, wg, D, S,
                                     (float4*)d_out, n4, (float*)d_out, osz);
    softmax_top1<<<S / 8, 256>>>(S);
    scan_laux_scatter<<<1, 1024>>>(S, S / 8, C, (float*)d_out, comb, disp, aux);
}

// round 3
// speedup vs baseline: 1.1592x; 1.1592x over previous
#include <cuda_runtime.h>

typedef unsigned long long ull;

#define NEXPERTS 64
#define S_MAX    8192
#define NZBLK    1792          // zero-fill blocks
#define NGBLK    256           // gemm blocks (S/64 * splitK = 128*2)

// static scratch (no allocations allowed)
__device__ float g_part[2u * S_MAX * NEXPERTS];          // split-K partial logits, 4MB
__device__ int   g_idx[S_MAX];
__device__ float g_gate[S_MAX];
__device__ float g_me_partial[(S_MAX / 8) * NEXPERTS];   // per-block softmax sums

__device__ __forceinline__ ull pack2(float lo, float hi) {
    ull r; asm("mov.b64 %0, {%1, %2};" : "=l"(r) : "f"(lo), "f"(hi)); return r;
}
__device__ __forceinline__ void ffma2(ull& d, ull a, ull b) {
    asm("fma.rn.f32x2 %0, %1, %2, %0;" : "+l"(d) : "l"(a), "l"(b));
}
__device__ __forceinline__ float2 unpack2(ull v) {
    float2 r; asm("mov.b64 {%0, %1}, %2;" : "=f"(r.x), "=f"(r.y) : "l"(v)); return r;
}

// ---------------------------------------------------------------------------
// Kernel 1: two block roles coscheduled in ONE launch.
//  - blocks [0, NGBLK): logits = x @ wg^T (split-K=2), pure FFMA2 work.
//  - blocks [NGBLK, NGBLK+NZBLK): streaming zero-fill of d_out (replaces the
//    537MB cudaMemset). Pure STG.128 stream -> saturates DRAM write while the
//    GEMM blocks use the fma pipes. Block-level fusion avoids the round-2
//    in-warp serialization.
// GEMM tile: 64 tokens x 64 experts, 256 threads, micro 4 tok x 4 exp,
// f32x2-packed accumulators over token pairs.
// ---------------------------------------------------------------------------
__global__ __launch_bounds__(256) void fused_gemm_zero(const float* __restrict__ x,
                                                       const float* __restrict__ wg,
                                                       int D, int S,
                                                       float4* __restrict__ zout,
                                                       size_t n4_total,
                                                       float* __restrict__ out,
                                                       size_t osz) {
    const int bid = blockIdx.x;
    const int tid = threadIdx.x;

    if (bid >= NGBLK) {
        // ---------------- zero-fill role ----------------
        const int zb = bid - NGBLK;
        const float4 z4 = make_float4(0.f, 0.f, 0.f, 0.f);
        const size_t stride = (size_t)NZBLK * 256;
        size_t i = (size_t)zb * 256 + tid;
        for (; i + 3 * stride < n4_total; i += 4 * stride) {
            zout[i]              = z4;
            zout[i + stride]     = z4;
            zout[i + 2 * stride] = z4;
            zout[i + 3 * stride] = z4;
        }
        for (; i < n4_total; i += stride) zout[i] = z4;
        if (zb == 0 && tid == 0) {       // tail floats (osz % 4)
            for (size_t t = n4_total * 4; t < osz; ++t) out[t] = 0.f;
        }
        return;
    }

    // ---------------- GEMM role ----------------
    __shared__ float As[32][68];   // [k][token], padded vs bank conflicts
    __shared__ float Bs[32][68];   // [k][expert]
    const int ty = tid >> 4;       // 0..15 -> tokens ty*4 .. ty*4+3
    const int tx = tid & 15;       // 0..15 -> experts tx*4 .. tx*4+3
    const int sblk   = bid & 127;           // S/64 = 128 token tiles
    const int kslice = bid >> 7;            // split-K index (0/1)
    const int s0   = sblk * 64;
    const int half = D >> 1;
    const int kbase = kslice * half;

    ull acc[2][4];
#pragma unroll
    for (int i = 0; i < 2; ++i)
#pragma unroll
        for (int j = 0; j < 4; ++j) acc[i][j] = 0ull;

    for (int kt = 0; kt < half; kt += 32) {
#pragma unroll
        for (int r = 0; r < 2; ++r) {
            int i   = tid + r * 256;       // 0..511 float4 groups
            int row = i >> 3;              // 0..63
            int k4  = (i & 7) << 2;        // 0,4,...,28
            float4 av = *(const float4*)(x  + (size_t)(s0 + row) * D + kbase + kt + k4);
            As[k4 + 0][row] = av.x; As[k4 + 1][row] = av.y;
            As[k4 + 2][row] = av.z; As[k4 + 3][row] = av.w;
            float4 bv = *(const float4*)(wg + (size_t)row * D + kbase + kt + k4);
            Bs[k4 + 0][row] = bv.x; Bs[k4 + 1][row] = bv.y;
            Bs[k4 + 2][row] = bv.z; Bs[k4 + 3][row] = bv.w;
        }
        __syncthreads();
#pragma unroll
        for (int k = 0; k < 32; ++k) {
            ulonglong2 A0 = *(const ulonglong2*)&As[k][ty * 4];
            ull a0 = A0.x, a1 = A0.y;                       // 4 tokens (2 pairs)
            float4 bv = *(const float4*)&Bs[k][tx * 4];
            ull b0 = pack2(bv.x, bv.x), b1 = pack2(bv.y, bv.y);
            ull b2 = pack2(bv.z, bv.z), b3 = pack2(bv.w, bv.w);
            ffma2(acc[0][0], a0, b0); ffma2(acc[0][1], a0, b1);
            ffma2(acc[0][2], a0, b2); ffma2(acc[0][3], a0, b3);
            ffma2(acc[1][0], a1, b0); ffma2(acc[1][1], a1, b1);
            ffma2(acc[1][2], a1, b2); ffma2(acc[1][3], a1, b3);
        }
        __syncthreads();
    }

    float* outp = g_part + (size_t)kslice * S * NEXPERTS;
#pragma unroll
    for (int i = 0; i < 2; ++i) {
        float2 c0 = unpack2(acc[i][0]);
        float2 c1 = unpack2(acc[i][1]);
        float2 c2 = unpack2(acc[i][2]);
        float2 c3 = unpack2(acc[i][3]);
        int t0 = s0 + ty * 4 + 2 * i;
        float4 lo = make_float4(c0.x, c1.x, c2.x, c3.x);
        float4 hi = make_float4(c0.y, c1.y, c2.y, c3.y);
        *(float4*)(outp + (size_t)t0 * NEXPERTS + tx * 4)       = lo;
        *(float4*)(outp + (size_t)(t0 + 1) * NEXPERTS + tx * 4) = hi;
    }
}

// ---------------------------------------------------------------------------
// Kernel 2: per-token softmax over 64 experts, top-1 (first max = argmax),
// gate = 1/sum(exp(l - max)). One warp per token. Emits deterministic
// per-block partial sums of gates for l_aux's "me".
// ---------------------------------------------------------------------------
__global__ __launch_bounds__(256) void softmax_top1(int S) {
    __shared__ float gsh[8][64];
    const int warp = threadIdx.x >> 5;
    const int lane = threadIdx.x & 31;
    const int t = blockIdx.x * 8 + warp;

    const float* p0 = g_part + (size_t)t * NEXPERTS;
    const float* p1 = g_part + (size_t)S * NEXPERTS + (size_t)t * NEXPERTS;
    float v0 = p0[lane]      + p1[lane];
    float v1 = p0[lane + 32] + p1[lane + 32];

    float m = fmaxf(v0, v1);
#pragma unroll
    for (int o = 16; o; o >>= 1) m = fmaxf(m, __shfl_xor_sync(0xffffffffu, m, o));
    float e0 = expf(v0 - m), e1 = expf(v1 - m);
    float s = e0 + e1;
#pragma unroll
    for (int o = 16; o; o >>= 1) s += __shfl_xor_sync(0xffffffffu, s, o);

    int ix = 1 << 30;
    if (v1 == m) ix = lane + 32;
    if (v0 == m) ix = lane;          // lower index wins (jnp.argmax semantics)
#pragma unroll
    for (int o = 16; o; o >>= 1) ix = min(ix, __shfl_xor_sync(0xffffffffu, ix, o));

    float inv = 1.0f / s;
    gsh[warp][lane]      = e0 * inv;
    gsh[warp][lane + 32] = e1 * inv;
    if (lane == 0) { g_idx[t] = ix; g_gate[t] = inv; }
    __syncthreads();
    if (threadIdx.x < 64) {
        float acc = 0.f;
#pragma unroll
        for (int w = 0; w < 8; ++w) acc += gsh[w][threadIdx.x];
        g_me_partial[(size_t)blockIdx.x * 64 + threadIdx.x] = acc;
    }
}

// ---------------------------------------------------------------------------
// Kernel 3 (single block, 1024 threads): per-expert ordered rank of each token
// (cumsum of one-hot), ce counts, me reduction, l_aux — AND the sparse scatter
// of gate / dispatch values directly into the (already-zeroed) output.
// Thread (e, g): expert e = tid&63, chunk g = tid>>6 of S/16 tokens.
// Everything reduced in fixed order -> deterministic.
// ---------------------------------------------------------------------------
__global__ __launch_bounds__(1024) void scan_laux_scatter(int S, int nb, int C,
                                                          float* __restrict__ out,
                                                          long long comb_off,
                                                          long long disp_off,
                                                          int write_aux) {
    const int e = threadIdx.x & 63;
    const int g = threadIdx.x >> 6;     // 0..15
    const int chunk = S >> 4;
    const int s0 = g * chunk;

    int cnt = 0;
    for (int s = s0; s < s0 + chunk; ++s) cnt += (g_idx[s] == e);

    __shared__ int   cnt_s[16][64];
    __shared__ float me_s[16][64];
    cnt_s[g][e] = cnt;
    __syncthreads();

    int base = 0, total = 0;
#pragma unroll
    for (int gg = 0; gg < 16; ++gg) {
        int c = cnt_s[gg][e];
        if (gg < g) base += c;
        total += c;
    }
    // walk tokens; for each token routed to expert e, rank = run; scatter if kept
    int run = base;
    for (int s = s0; s < s0 + chunk; ++s) {
        if (g_idx[s] == e) {
            if (run < C) {
                size_t pos = ((size_t)s * NEXPERTS + e) * (size_t)C + run;
                out[(size_t)comb_off + pos] = g_gate[s];
                if (disp_off >= 0)
                    out[(size_t)disp_off + pos] = 1.0f;
            }
            run++;
        }
    }

    float mp = 0.f;
    for (int b = g; b < nb; b += 16) mp += g_me_partial[(size_t)b * 64 + e];
    me_s[g][e] = mp;
    __syncthreads();
    if (g == 0) {
        float me = 0.f;
#pragma unroll
        for (int gg = 0; gg < 16; ++gg) me += me_s[gg][e];
        me /= (float)S;
        float ce = (float)total / (float)S;   // counts BEFORE capacity drop
        me_s[0][e] = me * ce;
    }
    __syncthreads();
    if (threadIdx.x == 0 && write_aux) {
        float sum = 0.f;
        for (int ee = 0; ee < 64; ++ee) sum += me_s[0][ee];
        out[0] = sum * (float)NEXPERTS;       // mean(me*ce)*E^2 = sum*E
    }
}

extern "C" void kernel_launch(void* const* d_in, const int* in_sizes, int n_in,
                              void* d_out, int out_size) {
    const float* x  = (const float*)d_in[0];
    const float* wg = (const float*)d_in[1];
    const int D = in_sizes[1] / NEXPERTS;
    const int S = in_sizes[0] / D;
    const int C = (S + NEXPERTS - 1) / NEXPERTS;   // capacity_factor = 1.0
    const size_t SEC = (size_t)S * NEXPERTS * C;
    const size_t osz = (size_t)out_size;

    // output layout: [l_aux(1)][combine(SEC)][dispatch(SEC)] when sizes match
    long long comb = 0, disp = -1; int aux = 0;
    if (osz >= 2 * SEC + 1)      { aux = 1; comb = 1; disp = 1 + (long long)SEC; }
    else if (osz >= 2 * SEC)     { comb = 0; disp = (long long)SEC; }

    const size_t n4 = osz >> 2;   // float4-aligned zero-fill amount

    fused_gemm_zero<<<NGBLK + NZBLK, 256>>>(x, wg, D, S,
                                            (float4*)d_out, n4, (float*)d_out, osz);
    softmax_top1<<<S / 8, 256>>>(S);
    scan_laux_scatter<<<1, 1024>>>(S, S / 8, C, (float*)d_out, comb, disp, aux);
}